// round 16
// baseline (speedup 1.0000x reference)
#include <cuda_runtime.h>
#include <cuda_bf16.h>
#include <math.h>
#include <stdint.h>

#define BATCH 64
#define NPTS  512
#define DIM   512
#define NIDS  32                 // track ids in [-1, 32)
#define MTILES 4
#define GRID  (BATCH * MTILES)   // 256 CTAs
#define DTHREADS 256
#define MROWS 128                // M per CTA
#define NB    96                 // B rows: 32 first + 32 second + j1 + j2 + pad
#define KC    128                // K chunk
#define NCHUNK (DIM / KC)        // 4
#define NKSTEP (KC / 16)         // 8 mma k-steps per chunk
#define NTILES (NB / 8)          // 12 n-tiles per warp

#define AS 136                   // padded bf16 row stride for A/B tiles
#define DS 100                   // padded fp32 row stride for D
#define OFF_A 0                                  // 128*136*2 = 34816
#define OFF_B (MROWS * AS * 2)                   // 34816
#define OFF_D 0                                  // 128*100*4 = 51200 (aliases A/B)
#define OFF_MISC (OFF_B + NB * AS * 2)           // 60928
#define SMEM_TOTAL (OFF_MISC + 1792)             // 62720

__device__ __constant__ float c_margin = 0.3f;

// global scratch — zero-initialized; last block resets.
__device__ float        g_tot;
__device__ int          g_cntall;
__device__ unsigned int g_ticket;

struct Misc {
    int rows_B[NB];
    int first[NIDS];
    int second[NIDS];
    int count[NIDS];
    int j1, j2, idj1, nvalid;
    float anrm2[MROWS];
    float bnrm2[NB];
    float tot;
    int   cnt;
};

__device__ __forceinline__ uint32_t smem_u32(const void* p) {
    uint32_t a;
    asm("{ .reg .u64 t; cvta.to.shared.u64 t, %1; cvt.u32.u64 %0, t; }"
        : "=r"(a) : "l"(p));
    return a;
}
__device__ __forceinline__ void ldsm_x4(uint32_t& r0, uint32_t& r1,
                                        uint32_t& r2, uint32_t& r3, uint32_t a) {
    asm volatile("ldmatrix.sync.aligned.m8n8.x4.shared.b16 {%0,%1,%2,%3}, [%4];"
                 : "=r"(r0), "=r"(r1), "=r"(r2), "=r"(r3) : "r"(a));
}
__device__ __forceinline__ void ldsm_x2(uint32_t& r0, uint32_t& r1, uint32_t a) {
    asm volatile("ldmatrix.sync.aligned.m8n8.x2.shared.b16 {%0,%1}, [%2];"
                 : "=r"(r0), "=r"(r1) : "r"(a));
}
__device__ __forceinline__ void mma_bf16(float* c, uint32_t a0, uint32_t a1,
                                         uint32_t a2, uint32_t a3,
                                         uint32_t b0, uint32_t b1) {
    asm volatile(
        "mma.sync.aligned.m16n8k16.row.col.f32.bf16.bf16.f32 "
        "{%0,%1,%2,%3},{%4,%5,%6,%7},{%8,%9},{%0,%1,%2,%3};"
        : "+f"(c[0]), "+f"(c[1]), "+f"(c[2]), "+f"(c[3])
        : "r"(a0), "r"(a1), "r"(a2), "r"(a3), "r"(b0), "r"(b1));
}
__device__ __forceinline__ float wredsum(float v) {
    #pragma unroll
    for (int o = 16; o > 0; o >>= 1) v += __shfl_xor_sync(0xFFFFFFFFu, v, o);
    return v;
}
__device__ __forceinline__ uint32_t pack2(float a, float b) {
    __nv_bfloat162 h = __floats2bfloat162_rn(a, b);
    return *reinterpret_cast<uint32_t*>(&h);
}

// ---------------------------------------------------------------------------
// R16: per-batch GEMM D = A.B^T via mma.sync bf16 (base-ISA HMMA; tcgen05 is
// not available in this build's PTX target). d^2 = |a|^2+|q|^2-2dot with
// EXACT fp32 norms accumulated during fp32->bf16 conversion. The 64MB feats
// stream becomes fully coalesced bulk loads with no per-anchor latency chain.
// ---------------------------------------------------------------------------
__global__ void __launch_bounds__(DTHREADS)
dist_kernel(const float* __restrict__ feats,
            const int*   __restrict__ ids,
            float*       __restrict__ out,
            int out_size)
{
    extern __shared__ char smem[];
    Misc* mi = (Misc*)(smem + OFF_MISC);
    const uint32_t sbase = smem_u32(smem);

    const int blk  = blockIdx.x;
    const int b    = blk >> 2;
    const int tm   = blk & 3;
    const int t    = threadIdx.x;
    const int wid  = t >> 5;
    const int lane = t & 31;

    // ---- init tables ----
    if (t < NIDS) {
        mi->first[t]  = 0x7fffffff;
        mi->second[t] = 0x7fffffff;
        mi->count[t]  = 0;
    }
    if (t == 0) {
        mi->j1 = 0x7fffffff; mi->j2 = 0x7fffffff;
        mi->nvalid = 0; mi->tot = 0.0f; mi->cnt = 0;
    }
    __syncthreads();

    const int* __restrict__ bid = ids + b * NPTS;

    // ---- pass 1: first per id, counts, first valid ----
    const int2 iv = ((const int2*)bid)[t];
    const int i0 = 2 * t, i1 = 2 * t + 1;
    if (iv.x >= 0) {
        atomicMin(&mi->first[iv.x], i0);
        atomicAdd(&mi->count[iv.x], 1);
        atomicMin(&mi->j1, i0);
    }
    if (iv.y >= 0) {
        atomicMin(&mi->first[iv.y], i1);
        atomicAdd(&mi->count[iv.y], 1);
        atomicMin(&mi->j1, i1);
    }
    int nv = __syncthreads_count(iv.x >= 0);
    nv    += __syncthreads_count(iv.y >= 0);
    if (t == 0) {
        mi->nvalid = nv;
        mi->idj1 = (mi->j1 < NPTS) ? bid[mi->j1] : -2;
    }
    __syncthreads();

    // ---- pass 2: second per id, j2 ----
    const int idj1 = mi->idj1;
    if (iv.x >= 0) {
        if (i0 != mi->first[iv.x]) atomicMin(&mi->second[iv.x], i0);
        if (iv.x != idj1)          atomicMin(&mi->j2, i0);
    }
    if (iv.y >= 0) {
        if (i1 != mi->first[iv.y]) atomicMin(&mi->second[iv.y], i1);
        if (iv.y != idj1)          atomicMin(&mi->j2, i1);
    }
    __syncthreads();

    // ---- B row list (clamped; pad rows -> row 0, unused) ----
    if (t < NB) {
        int r = 0;
        if (t < 32)       { const int f = mi->first[t];       r = (f < NPTS) ? f : 0; }
        else if (t < 64)  { const int s = mi->second[t - 32]; r = (s < NPTS) ? s : 0; }
        else if (t == 64) { r = (mi->j1 < NPTS) ? mi->j1 : 0; }
        else if (t == 65) { r = (mi->j2 < NPTS) ? mi->j2 : 0; }
        mi->rows_B[t] = r;
    }
    __syncthreads();

    const float* __restrict__ fb = feats + (size_t)b * NPTS * DIM;

    float acc[NTILES][4];
    #pragma unroll
    for (int j = 0; j < NTILES; ++j) {
        acc[j][0] = 0.0f; acc[j][1] = 0.0f; acc[j][2] = 0.0f; acc[j][3] = 0.0f;
    }

    // ---- K-chunk loop: convert -> mma ----
    for (int kc = 0; kc < NCHUNK; ++kc) {
        // A tile: warp w converts rows r == w (mod 8); one warp covers a full
        // 128-float row chunk (lane*4). Exact norm accumulated in fp32.
        #pragma unroll 4
        for (int j = 0; j < MROWS / 8; ++j) {
            const int r = wid + 8 * j;
            const float4 v = *(const float4*)(fb + ((size_t)(tm * MROWS + r)) * DIM
                                              + kc * KC + lane * 4);
            float pn = v.x * v.x + v.y * v.y;
            pn = fmaf(v.z, v.z, pn); pn = fmaf(v.w, v.w, pn);
            pn = wredsum(pn);
            if (lane == 0) {
                if (kc == 0) mi->anrm2[r] = pn; else mi->anrm2[r] += pn;
            }
            uint2 pk = { pack2(v.x, v.y), pack2(v.z, v.w) };
            *(uint2*)(smem + OFF_A + (r * AS + lane * 4) * 2) = pk;
        }
        // B tile: 96 gathered rows (L2-hot; duplicated across the batch's CTAs)
        #pragma unroll 4
        for (int j = 0; j < NB / 8; ++j) {
            const int c = wid + 8 * j;
            const int row = mi->rows_B[c];
            const float4 v = *(const float4*)(fb + (size_t)row * DIM
                                              + kc * KC + lane * 4);
            if (c < 66) {
                float pn = v.x * v.x + v.y * v.y;
                pn = fmaf(v.z, v.z, pn); pn = fmaf(v.w, v.w, pn);
                pn = wredsum(pn);
                if (lane == 0) {
                    if (kc == 0) mi->bnrm2[c] = pn; else mi->bnrm2[c] += pn;
                }
            }
            uint2 pk = { pack2(v.x, v.y), pack2(v.z, v.w) };
            *(uint2*)(smem + OFF_B + (c * AS + lane * 4) * 2) = pk;
        }
        __syncthreads();

        // mma: warp w computes D rows 16w..16w+15 x all 96 N
        #pragma unroll
        for (int s = 0; s < NKSTEP; ++s) {
            uint32_t a0, a1, a2, a3;
            const uint32_t aaddr = sbase + OFF_A +
                ((16 * wid + (lane & 15)) * AS + s * 16 + (lane >> 4) * 8) * 2;
            ldsm_x4(a0, a1, a2, a3, aaddr);
            #pragma unroll
            for (int nt = 0; nt < NTILES; ++nt) {
                uint32_t b0, b1;
                const uint32_t baddr = sbase + OFF_B +
                    ((nt * 8 + (lane & 7)) * AS + s * 16 + ((lane >> 3) & 1) * 8) * 2;
                ldsm_x2(b0, b1, baddr);
                mma_bf16(acc[nt], a0, a1, a2, a3, b0, b1);
            }
        }
        __syncthreads();    // tiles dead; safe to overwrite next chunk
    }

    // ---- D -> smem (aliases dead A/B tiles) ----
    float* sD = (float*)(smem + OFF_D);
    {
        const int row0 = 16 * wid + (lane >> 2);
        const int col0 = (lane & 3) * 2;
        #pragma unroll
        for (int nt = 0; nt < NTILES; ++nt) {
            const int col = nt * 8 + col0;
            sD[row0 * DS + col]           = acc[nt][0];
            sD[row0 * DS + col + 1]       = acc[nt][1];
            sD[(row0 + 8) * DS + col]     = acc[nt][2];
            sD[(row0 + 8) * DS + col + 1] = acc[nt][3];
        }
    }
    __syncthreads();

    // ---- per-anchor hinge (thread t < 128 = local row t) ----
    float w_tot = 0.0f;
    int   w_cnt = 0;
    if (t < MROWS) {
        const int ig = tm * MROWS + t;
        const int id = bid[ig];
        if (id >= 0) {
            const int cm = mi->count[id];
            if (cm >= 2 && mi->nvalid > cm) {
                const bool isf = (ig == mi->first[id]);
                const float pd  = sD[t * DS + (isf ? 32 + id : id)];
                const float pn2 = isf ? mi->bnrm2[32 + id] : mi->bnrm2[id];
                const int  nc   = (idj1 != id) ? 64 : 65;
                const float nd  = sD[t * DS + nc];
                const float nn2 = mi->bnrm2[nc];
                const float an2 = mi->anrm2[t];
                const float dap = sqrtf(fmaxf(fmaf(-2.0f, pd, an2 + pn2), 0.0f));
                const float dan = sqrtf(fmaxf(fmaf(-2.0f, nd, an2 + nn2), 0.0f));
                const float per = dap - dan + c_margin;
                if (per > 0.0f) w_tot = per;
                w_cnt = 1;
            }
        }
    }
    w_tot = wredsum(w_tot);
    {
        int c = w_cnt;
        #pragma unroll
        for (int o = 16; o > 0; o >>= 1) c += __shfl_xor_sync(0xFFFFFFFFu, c, o);
        w_cnt = c;
    }
    if (lane == 0) {
        atomicAdd(&mi->tot, w_tot);
        atomicAdd(&mi->cnt, w_cnt);
    }
    __syncthreads();

    // ---- ticketed finish ----
    if (t == 0) {
        atomicAdd(&g_tot, mi->tot);
        atomicAdd(&g_cntall, mi->cnt);
        __threadfence();
        const unsigned int old = atomicAdd(&g_ticket, 1u);
        if (old == GRID - 1) {
            __threadfence();
            const float T = g_tot;
            const int   C = g_cntall;
            const float loss = (C > 0) ? (T / (float)C) : 0.0f;
            if (out_size > 0) out[0] = loss;   // tracking_loss
            if (out_size > 1) out[1] = loss;   // loss_triplet
            if (out_size > 2) out[2] = 0.0f;   // loss_id
            g_tot = 0.0f; g_cntall = 0; g_ticket = 0;
            __threadfence();
        }
    }
}

extern "C" void kernel_launch(void* const* d_in, const int* in_sizes, int n_in,
                              void* d_out, int out_size)
{
    const float* feats = (const float*)d_in[0];
    const int*   ids   = (const int*)d_in[1];
    float*       out   = (float*)d_out;

    cudaFuncSetAttribute(dist_kernel,
                         cudaFuncAttributeMaxDynamicSharedMemorySize, SMEM_TOTAL);
    dist_kernel<<<GRID, DTHREADS, SMEM_TOTAL>>>(feats, ids, out, out_size);
}

// round 17
// speedup vs baseline: 1.2039x; 1.2039x over previous
#include <cuda_runtime.h>
#include <cuda_bf16.h>
#include <math.h>
#include <stdint.h>

#define BATCH 64
#define NPTS  512
#define DIM   512
#define NIDS  32                 // track ids in [-1, 32)
#define MTILES 4
#define GRID  (BATCH * MTILES)   // 256 CTAs (all resident at 2/SM)
#define DTHREADS 256
#define MROWS 128                // M per CTA
#define NB    72                 // B rows: 32 first + 32 second + j1 + j2 + 6 pad
#define KC    128                // K chunk
#define NCHUNK (DIM / KC)        // 4
#define NKSTEP (KC / 16)         // 8 mma k-steps per chunk
#define NTILES (NB / 8)          // 9 n-tiles per warp

#define AS 136                   // padded bf16 row stride for A/B tiles
#define DS 76                    // padded fp32 row stride for D
#define OFF_A 0                                  // 128*136*2 = 34816
#define OFF_B (MROWS * AS * 2)                   // 34816
#define OFF_D 0                                  // 128*76*4 = 38912 (aliases A/B)
#define OFF_MISC (OFF_B + NB * AS * 2)           // 54400
#define SMEM_TOTAL (OFF_MISC + 1024)             // 55424

__device__ __constant__ float c_margin = 0.3f;

// global scratch — zero-initialized; last block resets.
__device__ float        g_tot;
__device__ int          g_cntall;
__device__ unsigned int g_ticket;

struct Misc {
    int rows_B[NB];
    int first[NIDS];
    int second[NIDS];
    int count[NIDS];
    int j1, j2, idj1, nvalid;
    float bnrm2[NB];
    float tot;
    int   cnt;
};

__device__ __forceinline__ uint32_t smem_u32(const void* p) {
    uint32_t a;
    asm("{ .reg .u64 t; cvta.to.shared.u64 t, %1; cvt.u32.u64 %0, t; }"
        : "=r"(a) : "l"(p));
    return a;
}
__device__ __forceinline__ void ldsm_x4(uint32_t& r0, uint32_t& r1,
                                        uint32_t& r2, uint32_t& r3, uint32_t a) {
    asm volatile("ldmatrix.sync.aligned.m8n8.x4.shared.b16 {%0,%1,%2,%3}, [%4];"
                 : "=r"(r0), "=r"(r1), "=r"(r2), "=r"(r3) : "r"(a));
}
__device__ __forceinline__ void ldsm_x2(uint32_t& r0, uint32_t& r1, uint32_t a) {
    asm volatile("ldmatrix.sync.aligned.m8n8.x2.shared.b16 {%0,%1}, [%2];"
                 : "=r"(r0), "=r"(r1) : "r"(a));
}
__device__ __forceinline__ void mma_bf16(float* c, uint32_t a0, uint32_t a1,
                                         uint32_t a2, uint32_t a3,
                                         uint32_t b0, uint32_t b1) {
    asm volatile(
        "mma.sync.aligned.m16n8k16.row.col.f32.bf16.bf16.f32 "
        "{%0,%1,%2,%3},{%4,%5,%6,%7},{%8,%9},{%0,%1,%2,%3};"
        : "+f"(c[0]), "+f"(c[1]), "+f"(c[2]), "+f"(c[3])
        : "r"(a0), "r"(a1), "r"(a2), "r"(a3), "r"(b0), "r"(b1));
}
__device__ __forceinline__ float wredsum(float v) {
    #pragma unroll
    for (int o = 16; o > 0; o >>= 1) v += __shfl_xor_sync(0xFFFFFFFFu, v, o);
    return v;
}
__device__ __forceinline__ uint32_t pack2(float a, float b) {
    __nv_bfloat162 h = __floats2bfloat162_rn(a, b);
    return *reinterpret_cast<uint32_t*>(&h);
}
// accumulate |bf16x2 pair|^2 from a packed uint32 into acc (fp32)
__device__ __forceinline__ void nrm_bf2(uint32_t pk, float& acc) {
    const float2 f = __bfloat1622float2(*reinterpret_cast<__nv_bfloat162*>(&pk));
    acc = fmaf(f.x, f.x, acc);
    acc = fmaf(f.y, f.y, acc);
}

// ---------------------------------------------------------------------------
// R17: R16's HMMA GEMM with the two bleeding points fixed.
//  (1) NO shuffle reductions in the hot loop: norms are computed FROM the
//      bf16 tiles (thread-per-row scan, register accumulate). This makes
//      d^2 = |a~|^2+|q~|^2-2 a~.q~ the EXACT distance of bf16-rounded rows
//      (bf16 products are exact in fp32) -> loss rel-err ~1e-4.
//  (2) NB 96->72 (66 used): 25% less MMA + B-convert work, fewer acc regs.
// ---------------------------------------------------------------------------
__global__ void __launch_bounds__(DTHREADS)
dist_kernel(const float* __restrict__ feats,
            const int*   __restrict__ ids,
            float*       __restrict__ out,
            int out_size)
{
    extern __shared__ char smem[];
    Misc* mi = (Misc*)(smem + OFF_MISC);
    const uint32_t sbase = smem_u32(smem);

    const int blk  = blockIdx.x;
    const int b    = blk >> 2;
    const int tm   = blk & 3;
    const int t    = threadIdx.x;
    const int wid  = t >> 5;
    const int lane = t & 31;

    // ---- init tables ----
    if (t < NIDS) {
        mi->first[t]  = 0x7fffffff;
        mi->second[t] = 0x7fffffff;
        mi->count[t]  = 0;
    }
    if (t == 0) {
        mi->j1 = 0x7fffffff; mi->j2 = 0x7fffffff;
        mi->nvalid = 0; mi->tot = 0.0f; mi->cnt = 0;
    }
    __syncthreads();

    const int* __restrict__ bid = ids + b * NPTS;

    // ---- pass 1: first per id, counts, first valid ----
    const int2 iv = ((const int2*)bid)[t];
    const int i0 = 2 * t, i1 = 2 * t + 1;
    if (iv.x >= 0) {
        atomicMin(&mi->first[iv.x], i0);
        atomicAdd(&mi->count[iv.x], 1);
        atomicMin(&mi->j1, i0);
    }
    if (iv.y >= 0) {
        atomicMin(&mi->first[iv.y], i1);
        atomicAdd(&mi->count[iv.y], 1);
        atomicMin(&mi->j1, i1);
    }
    int nv = __syncthreads_count(iv.x >= 0);
    nv    += __syncthreads_count(iv.y >= 0);
    if (t == 0) {
        mi->nvalid = nv;
        mi->idj1 = (mi->j1 < NPTS) ? bid[mi->j1] : -2;
    }
    __syncthreads();

    // ---- pass 2: second per id, j2 ----
    const int idj1 = mi->idj1;
    if (iv.x >= 0) {
        if (i0 != mi->first[iv.x]) atomicMin(&mi->second[iv.x], i0);
        if (iv.x != idj1)          atomicMin(&mi->j2, i0);
    }
    if (iv.y >= 0) {
        if (i1 != mi->first[iv.y]) atomicMin(&mi->second[iv.y], i1);
        if (iv.y != idj1)          atomicMin(&mi->j2, i1);
    }
    __syncthreads();

    // ---- B row list (clamped; pad rows -> row 0, unused) ----
    if (t < NB) {
        int r = 0;
        if (t < 32)       { const int f = mi->first[t];       r = (f < NPTS) ? f : 0; }
        else if (t < 64)  { const int s = mi->second[t - 32]; r = (s < NPTS) ? s : 0; }
        else if (t == 64) { r = (mi->j1 < NPTS) ? mi->j1 : 0; }
        else if (t == 65) { r = (mi->j2 < NPTS) ? mi->j2 : 0; }
        mi->rows_B[t] = r;
    }
    __syncthreads();

    const float* __restrict__ fb = feats + (size_t)b * NPTS * DIM;

    float acc[NTILES][4];
    #pragma unroll
    for (int j = 0; j < NTILES; ++j) {
        acc[j][0] = 0.0f; acc[j][1] = 0.0f; acc[j][2] = 0.0f; acc[j][3] = 0.0f;
    }
    float my_nrm = 0.0f;          // thread t: |row t|^2 (A for t<128, B for 128..199)

    // ---- K-chunk loop: convert -> mma + norm scan ----
    for (int kc = 0; kc < NCHUNK; ++kc) {
        // A tile: warp w converts rows r == w (mod 8); pure load->cvt->store.
        #pragma unroll 4
        for (int j = 0; j < MROWS / 8; ++j) {
            const int r = wid + 8 * j;
            const float4 v = *(const float4*)(fb + ((size_t)(tm * MROWS + r)) * DIM
                                              + kc * KC + lane * 4);
            uint2 pk = { pack2(v.x, v.y), pack2(v.z, v.w) };
            *(uint2*)(smem + OFF_A + (r * AS + lane * 4) * 2) = pk;
        }
        // B tile: 72 gathered rows (L2-hot across the batch's 4 CTAs)
        #pragma unroll 3
        for (int j = 0; j < NB / 8; ++j) {
            const int c = wid + 8 * j;
            const float4 v = *(const float4*)(fb + (size_t)mi->rows_B[c] * DIM
                                              + kc * KC + lane * 4);
            uint2 pk = { pack2(v.x, v.y), pack2(v.z, v.w) };
            *(uint2*)(smem + OFF_B + (c * AS + lane * 4) * 2) = pk;
        }
        __syncthreads();

        // mma: warp w computes D rows 16w..16w+15 x all 72 N
        #pragma unroll
        for (int s = 0; s < NKSTEP; ++s) {
            uint32_t a0, a1, a2, a3;
            const uint32_t aaddr = sbase + OFF_A +
                ((16 * wid + (lane & 15)) * AS + s * 16 + (lane >> 4) * 8) * 2;
            ldsm_x4(a0, a1, a2, a3, aaddr);
            #pragma unroll
            for (int nt = 0; nt < NTILES; ++nt) {
                uint32_t b0, b1;
                const uint32_t baddr = sbase + OFF_B +
                    ((nt * 8 + (lane & 7)) * AS + s * 16 + ((lane >> 3) & 1) * 8) * 2;
                ldsm_x2(b0, b1, baddr);
                mma_bf16(acc[nt], a0, a1, a2, a3, b0, b1);
            }
        }

        // norm scan: thread-per-row over the bf16 tiles (no reductions)
        if (t < MROWS + NB) {
            const char* rowp = (t < MROWS)
                ? (smem + OFF_A + t * AS * 2)
                : (smem + OFF_B + (t - MROWS) * AS * 2);
            #pragma unroll
            for (int q = 0; q < KC / 8; ++q) {        // 16 uint4 = 128 bf16
                const uint4 u = *(const uint4*)(rowp + q * 16);
                nrm_bf2(u.x, my_nrm); nrm_bf2(u.y, my_nrm);
                nrm_bf2(u.z, my_nrm); nrm_bf2(u.w, my_nrm);
            }
        }
        __syncthreads();          // tiles dead; safe to overwrite next chunk
    }

    // ---- publish B norms (A norm stays in the owning thread's register) ----
    if (t >= MROWS && t < MROWS + NB) mi->bnrm2[t - MROWS] = my_nrm;

    // ---- D -> smem (aliases dead A/B tiles) ----
    float* sD = (float*)(smem + OFF_D);
    {
        const int row0 = 16 * wid + (lane >> 2);
        const int col0 = (lane & 3) * 2;
        #pragma unroll
        for (int nt = 0; nt < NTILES; ++nt) {
            const int col = nt * 8 + col0;
            sD[row0 * DS + col]           = acc[nt][0];
            sD[row0 * DS + col + 1]       = acc[nt][1];
            sD[(row0 + 8) * DS + col]     = acc[nt][2];
            sD[(row0 + 8) * DS + col + 1] = acc[nt][3];
        }
    }
    __syncthreads();

    // ---- per-anchor hinge (thread t < 128 = local row t; an2 in register) ----
    float w_tot = 0.0f;
    int   w_cnt = 0;
    if (t < MROWS) {
        const int ig = tm * MROWS + t;
        const int id = bid[ig];
        if (id >= 0) {
            const int cm = mi->count[id];
            if (cm >= 2 && mi->nvalid > cm) {
                const bool isf = (ig == mi->first[id]);
                const float pd  = sD[t * DS + (isf ? 32 + id : id)];
                const float pn2 = isf ? mi->bnrm2[32 + id] : mi->bnrm2[id];
                const int  nc   = (idj1 != id) ? 64 : 65;
                const float nd  = sD[t * DS + nc];
                const float nn2 = mi->bnrm2[nc];
                const float dap = sqrtf(fmaxf(fmaf(-2.0f, pd, my_nrm + pn2), 0.0f));
                const float dan = sqrtf(fmaxf(fmaf(-2.0f, nd, my_nrm + nn2), 0.0f));
                const float per = dap - dan + c_margin;
                if (per > 0.0f) w_tot = per;
                w_cnt = 1;
            }
        }
    }
    w_tot = wredsum(w_tot);
    {
        int c = w_cnt;
        #pragma unroll
        for (int o = 16; o > 0; o >>= 1) c += __shfl_xor_sync(0xFFFFFFFFu, c, o);
        w_cnt = c;
    }
    if (lane == 0) {
        atomicAdd(&mi->tot, w_tot);
        atomicAdd(&mi->cnt, w_cnt);
    }
    __syncthreads();

    // ---- ticketed finish ----
    if (t == 0) {
        atomicAdd(&g_tot, mi->tot);
        atomicAdd(&g_cntall, mi->cnt);
        __threadfence();
        const unsigned int old = atomicAdd(&g_ticket, 1u);
        if (old == GRID - 1) {
            __threadfence();
            const float T = g_tot;
            const int   C = g_cntall;
            const float loss = (C > 0) ? (T / (float)C) : 0.0f;
            if (out_size > 0) out[0] = loss;   // tracking_loss
            if (out_size > 1) out[1] = loss;   // loss_triplet
            if (out_size > 2) out[2] = 0.0f;   // loss_id
            g_tot = 0.0f; g_cntall = 0; g_ticket = 0;
            __threadfence();
        }
    }
}

extern "C" void kernel_launch(void* const* d_in, const int* in_sizes, int n_in,
                              void* d_out, int out_size)
{
    const float* feats = (const float*)d_in[0];
    const int*   ids   = (const int*)d_in[1];
    float*       out   = (float*)d_out;

    cudaFuncSetAttribute(dist_kernel,
                         cudaFuncAttributeMaxDynamicSharedMemorySize, SMEM_TOTAL);
    dist_kernel<<<GRID, DTHREADS, SMEM_TOTAL>>>(feats, ids, out, out_size);
}